// round 16
// baseline (speedup 1.0000x reference)
#include <cuda_runtime.h>

#define BB 4
#define LL 256
#define DD 256

// scratch (allocation-free contract: __device__ globals, zero-initialized)
__device__ float g_Sdep[4][BB * LL * DD];  // partials: j quarter q
__device__ float g_Wt[DD * DD];            // W transposed: Wt[d*256 + o]

// dataflow sync state (must be 0 at every launch; last out block resets)
__device__ volatile int g_depcnt[BB * LL];   // quarters done per row (==4 ready)
__device__ volatile int g_wtcnt;             // transpose blocks done (32)
__device__ int g_outcnt;                     // out blocks done (128)

// ---- packed f32x2 helpers (Blackwell FFMA2) --------------------------------
__device__ __forceinline__ unsigned long long splat2(float s) {
    unsigned long long r;
    asm("mov.b64 %0, {%1, %1};" : "=l"(r) : "f"(s));
    return r;
}
__device__ __forceinline__ void fma2(unsigned long long& acc,
                                     unsigned long long a,
                                     unsigned long long b) {
    asm("fma.rn.f32x2 %0, %1, %2, %0;" : "+l"(acc) : "l"(a), "l"(b));
}
__device__ __forceinline__ void unpk2(float& lo, float& hi, unsigned long long v) {
    asm("mov.b64 {%0, %1}, %2;" : "=f"(lo), "=f"(hi) : "l"(v));
}

// smem layout (union across roles); max user = out stage
#define OFF_SS    0        // Ssm [8][264] floats = 8448 B (also adjs/red)
#define OFF_WTS   8448     // Wts [2][16][64] float4 = 32768 B
#define OFF_AA    41216    // A [8] floats
#define OFF_LASTF 41248    // int
#define SMEM_SZ   41280

// ---------------------------------------------------------------------------
// k_mega: ONE kernel, grid 4256 x 256 (champion structure + quarter-row dep).
//   bx in [0,128)    : S0 gemm into smem -> wait(Wt, own 8 rows cnt==4)
//                      -> S = S0 + 4 partials -> out GEMM (dbuf smem Wt, FFMA2)
//   bx in [128,160)  : W transpose -> g_Wt (2 tiles each), wtcnt++
//   bx in [160,4256) : dep QUARTER-row: e=bx-160, row=e>>2, q=e&3;
//                      partial over 64 j's -> g_Sdep[q], depcnt[row]++
// Quarter quanta (~4.4us) pack the DRAM stream tighter; the max-of-8-rows
// wait each out tile pays shrinks with the quantum.
// ---------------------------------------------------------------------------
__global__ void __launch_bounds__(256, 4)
k_mega(const float* __restrict__ text,
       const float* __restrict__ adj,
       const float* __restrict__ dep,
       const float* __restrict__ W,
       const float* __restrict__ bias,
       float* __restrict__ out) {
    const int bx = blockIdx.x;
    const int t  = threadIdx.x;

    __shared__ __align__(16) char smraw[SMEM_SZ];

    // =========================== transpose role ===========================
    if (bx >= 128 && bx < 160) {
        float (*tile)[33] = (float (*)[33])smraw;
        const int tx = t & 31, ty = t >> 5;   // (32, 8)
#pragma unroll 1
        for (int pass = 0; pass < 2; pass++) {
            const int bb = (bx - 128) + pass * 32;
            const int d0 = (bb & 7) * 32, o0 = (bb >> 3) * 32;
#pragma unroll
            for (int k = 0; k < 32; k += 8)
                tile[ty + k][tx] = W[(o0 + ty + k) * DD + (d0 + tx)];
            __syncthreads();
#pragma unroll
            for (int k = 0; k < 32; k += 8)
                g_Wt[(d0 + ty + k) * DD + (o0 + tx)] = tile[tx][ty + k];
            __syncthreads();
        }
        __threadfence();
        __syncthreads();
        if (t == 0) atomicAdd((int*)&g_wtcnt, 1);
        return;
    }

    // ========================= dep quarter-row role ========================
    if (bx >= 160) {
        const int e  = bx - 160;          // 0..4095
        const int id = e >> 2;            // global row = b*256 + i
        const int q  = e & 3;
        const int b  = id >> 8;
        const int i  = id & 255;
        const int jj = t >> 6;
        const int d4 = t & 63;

        float*  adjs1 = (float*)smraw;                  // [256]
        float4* red   = (float4*)(smraw + 1024);        // [4][64]

        adjs1[t] = adj[(b * LL + i) * LL + t];
        __syncthreads();

        const int jbase = q * 64 + jj * 16;   // 16 j's per thread-group
        const float4* p = (const float4*)dep
                        + (((size_t)(b * LL + jbase) * LL + i) << 6) + d4;
        const size_t jstride = (size_t)LL << 6;   // 16384 float4 per j

        float4 acc = make_float4(0.f, 0.f, 0.f, 0.f);

#pragma unroll 1
        for (int js = 0; js < 16; js += 8) {
            float4 dv[8];
#pragma unroll
            for (int u = 0; u < 8; u++)
                dv[u] = __ldcs(p + (size_t)u * jstride);   // 8 LDG.128 in flight
            p += jstride * 8;
#pragma unroll
            for (int u = 0; u < 8; u++) {
                const float a = adjs1[jbase + js + u];
                acc.x += a * dv[u].x;
                acc.y += a * dv[u].y;
                acc.z += a * dv[u].z;
                acc.w += a * dv[u].w;
            }
        }

        red[(jj << 6) + d4] = acc;
        __syncthreads();
        if (t < 64) {
            float4 r0 = red[t], r1 = red[64 + t], r2 = red[128 + t], r3 = red[192 + t];
            float4 s;
            s.x = (r0.x + r1.x) + (r2.x + r3.x);
            s.y = (r0.y + r1.y) + (r2.y + r3.y);
            s.z = (r0.z + r1.z) + (r2.z + r3.z);
            s.w = (r0.w + r1.w) + (r2.w + r3.w);
            ((float4*)g_Sdep[q])[(id << 6) + t] = s;
        }
        __threadfence();      // release: partial visible before counter bump
        __syncthreads();
        if (t == 0) atomicAdd((int*)&g_depcnt[id], 1);
        return;
    }

    // ================== combined gemm -> wait -> out role ==================
    const int row0 = bx * 8;              // global rows row0..row0+7
    const int b    = row0 >> 8;

    float* Ss = (float*)smraw;                        // [8][264] after gemm
    float* Aa = (float*)(smraw + OFF_AA);             // [8]
    int*   lastf = (int*)(smraw + OFF_LASTF);

    {   // ---- S0 = adj @ text (8 rows) -> smem, A -> smem ----
        float (*adjs)[LL] = (float (*)[LL])smraw;
        const float* adjg = adj + (size_t)row0 * LL;
#pragma unroll
        for (int r = 0; r < 8; r++) adjs[r][t] = adjg[r * LL + t];
        __syncthreads();

        {   // A row sums: warp w reduces adjs[w]
            const int warp = t >> 5, lane = t & 31;
            float s = 0.f;
#pragma unroll
            for (int k = 0; k < 8; k++) s += adjs[warp][lane + 32 * k];
#pragma unroll
            for (int off = 16; off; off >>= 1)
                s += __shfl_xor_sync(0xffffffffu, s, off);
            if (lane == 0) Aa[warp] = s;
        }

        const int o4 = t & 63;
        const int rg = t >> 6;
        const int r0 = rg * 2, r1 = r0 + 1;

        const float4* text4 = (const float4*)text + ((size_t)b * LL << 6) + o4;
        float4 acc0 = make_float4(0.f, 0.f, 0.f, 0.f);
        float4 acc1 = make_float4(0.f, 0.f, 0.f, 0.f);

#pragma unroll 1
        for (int j = 0; j < LL; j += 4) {
            float4 tv[4];
#pragma unroll
            for (int u = 0; u < 4; u++) tv[u] = text4[(j + u) << 6];
#pragma unroll
            for (int u = 0; u < 4; u++) {
                const float a0 = adjs[r0][j + u];
                const float a1 = adjs[r1][j + u];
                acc0.x += a0 * tv[u].x;  acc0.y += a0 * tv[u].y;
                acc0.z += a0 * tv[u].z;  acc0.w += a0 * tv[u].w;
                acc1.x += a1 * tv[u].x;  acc1.y += a1 * tv[u].y;
                acc1.z += a1 * tv[u].z;  acc1.w += a1 * tv[u].w;
            }
        }
        __syncthreads();   // all adjs reads done; safe to overwrite with Ssm
        *(float4*)&Ss[r0 * 264 + (o4 << 2)] = acc0;
        *(float4*)&Ss[r1 * 264 + (o4 << 2)] = acc1;
    }

    // ---- wait for Wt and all four quarters of our 8 rows ----
    if (t == 0) {
        while (g_wtcnt < 32) __nanosleep(128);
#pragma unroll 1
        for (int r = 0; r < 8; r++)
            while (g_depcnt[row0 + r] < 4) __nanosleep(128);
    }
    __syncthreads();
    __threadfence();   // acquire: order subsequent reads after flag observation

    // ---- S += sum of 4 partials (8 rows) ----
    {
        const float4* S0p = (const float4*)(g_Sdep[0] + (size_t)row0 * DD);
        const float4* S1p = (const float4*)(g_Sdep[1] + (size_t)row0 * DD);
        const float4* S2p = (const float4*)(g_Sdep[2] + (size_t)row0 * DD);
        const float4* S3p = (const float4*)(g_Sdep[3] + (size_t)row0 * DD);
#pragma unroll
        for (int k = 0; k < 2; k++) {
            const int idx = t + 256 * k;
            const int rr = idx >> 6, cc = idx & 63;
            float4 c0 = S0p[idx], c1 = S1p[idx], c2 = S2p[idx], c3 = S3p[idx];
            float4* pp = (float4*)&Ss[rr * 264 + (cc << 2)];
            float4 a = *pp;
            a.x += (c0.x + c1.x) + (c2.x + c3.x);
            a.y += (c0.y + c1.y) + (c2.y + c3.y);
            a.z += (c0.z + c1.z) + (c2.z + c3.z);
            a.w += (c0.w + c1.w) + (c2.w + c3.w);
            *pp = a;
        }
    }
    __syncthreads();

    // ---- out compute: 8 rows x 256 cols, double-buffered smem Wt + FFMA2 ----
    {
        float4 (*Wts)[16][64] = (float4 (*)[16][64])(smraw + OFF_WTS);
        const int c4 = t & 63;
        const int rh = t >> 6;
        const int rr0 = rh * 2, rr1 = rr0 + 1;
        const float4* Wtg = (const float4*)g_Wt;

        float4 pre[4];
#pragma unroll
        for (int k = 0; k < 4; k++)
            pre[k] = Wtg[((rh + 4 * k) << 6) + c4];

        unsigned long long aL0 = 0ull, aH0 = 0ull, aL1 = 0ull, aH1 = 0ull;

#pragma unroll 1
        for (int ch = 0; ch < 16; ch++) {
            const int buf = ch & 1;
#pragma unroll
            for (int k = 0; k < 4; k++)
                Wts[buf][rh + 4 * k][c4] = pre[k];
            __syncthreads();

            if (ch < 15) {
                const int dbase = (ch + 1) * 16;
#pragma unroll
                for (int k = 0; k < 4; k++)
                    pre[k] = Wtg[((dbase + rh + 4 * k) << 6) + c4];
            }

            const int dc = ch * 16;
#pragma unroll
            for (int d = 0; d < 16; d++) {
                const ulonglong2 w = *(const ulonglong2*)&Wts[buf][d][c4];
                const unsigned long long sp0 = splat2(Ss[rr0 * 264 + dc + d]);
                const unsigned long long sp1 = splat2(Ss[rr1 * 264 + dc + d]);
                fma2(aL0, w.x, sp0);  fma2(aH0, w.y, sp0);
                fma2(aL1, w.x, sp1);  fma2(aH1, w.y, sp1);
            }
            __syncthreads();
        }

        float4 res0, res1;
        unpk2(res0.x, res0.y, aL0);  unpk2(res0.z, res0.w, aH0);
        unpk2(res1.x, res1.y, aL1);  unpk2(res1.z, res1.w, aH1);

        const float4 bi = ((const float4*)bias)[c4];
        const float  a0 = Aa[rr0];
        const float  a1 = Aa[rr1];
        res0.x += a0 * bi.x;  res0.y += a0 * bi.y;
        res0.z += a0 * bi.z;  res0.w += a0 * bi.w;
        res1.x += a1 * bi.x;  res1.y += a1 * bi.y;
        res1.z += a1 * bi.z;  res1.w += a1 * bi.w;

        ((float4*)(out + (size_t)(row0 + rr0) * DD))[c4] = res0;
        ((float4*)(out + (size_t)(row0 + rr1) * DD))[c4] = res1;
    }

    // ---- last out block resets all sync state for the next graph replay ----
    __syncthreads();
    if (t == 0) *lastf = (atomicAdd(&g_outcnt, 1) == 127) ? 1 : 0;
    __syncthreads();
    if (*lastf) {
        for (int i = t; i < BB * LL; i += 256) g_depcnt[i] = 0;
        if (t == 0) { g_wtcnt = 0; g_outcnt = 0; }
    }
}

// ---------------------------------------------------------------------------
extern "C" void kernel_launch(void* const* d_in, const int* in_sizes, int n_in,
                              void* d_out, int out_size) {
    const float* text = (const float*)d_in[0];  // [4,256,256]
    const float* adj  = (const float*)d_in[1];  // [4,256,256]
    const float* dep  = (const float*)d_in[2];  // [4,256,256,256]
    const float* W    = (const float*)d_in[3];  // [256,256]
    const float* bias = (const float*)d_in[4];  // [256]
    float* out = (float*)d_out;                 // [4,256,256]

    k_mega<<<160 + 4 * BB * LL, 256>>>(text, adj, dep, W, bias, out);
}

// round 17
// speedup vs baseline: 1.0387x; 1.0387x over previous
#include <cuda_runtime.h>

#define BB 4
#define LL 256
#define DD 256

// scratch (allocation-free contract: __device__ globals, zero-initialized)
__device__ float g_SdepA[BB * LL * DD];  // partial: j in [0,128)
__device__ float g_SdepB[BB * LL * DD];  // partial: j in [128,256)
__device__ float g_Wt[DD * DD];          // W transposed: Wt[d*256 + o]

// dataflow sync state (must be 0 at every launch; last out block resets)
__device__ volatile int g_depcnt[BB * LL];   // halves done per row (==2 ready)
__device__ volatile int g_wtcnt;             // transpose blocks done (32)
__device__ int g_outcnt;                     // out blocks done (256)

// ---- packed f32x2 helpers (Blackwell FFMA2) --------------------------------
__device__ __forceinline__ unsigned long long splat2(float s) {
    unsigned long long r;
    asm("mov.b64 %0, {%1, %1};" : "=l"(r) : "f"(s));
    return r;
}
__device__ __forceinline__ void fma2(unsigned long long& acc,
                                     unsigned long long a,
                                     unsigned long long b) {
    asm("fma.rn.f32x2 %0, %1, %2, %0;" : "+l"(acc) : "l"(a), "l"(b));
}
__device__ __forceinline__ void add2(unsigned long long& acc,
                                     unsigned long long v) {
    asm("add.rn.f32x2 %0, %0, %1;" : "+l"(acc) : "l"(v));
}
__device__ __forceinline__ void unpk2(float& lo, float& hi, unsigned long long v) {
    asm("mov.b64 {%0, %1}, %2;" : "=f"(lo), "=f"(hi) : "l"(v));
}

// smem layout (union across roles); max user = out stage
#define OFF_SS    0        // Ssm [8][264] floats = 8448 B (also adjs/red)
#define OFF_WTS   8448     // Wts [2][2][16][32] float4 = 32768 B (also Red)
#define OFF_AA    41216    // A [8] floats
#define OFF_LASTF 41248    // int
#define SMEM_SZ   41280

// ---------------------------------------------------------------------------
// k_mega: ONE kernel, grid 2336 x 256 (r15 champion + column-split out).
//   bx in [0,256)    : combined block: tile=bx>>1, nt=bx&1 (output col half).
//                      S0 gemm (full d) into smem -> wait(Wt, 8 rows cnt==2)
//                      -> S = S0+SdA+SdB -> out GEMM for cols [128nt,128nt+128)
//                      with threads d-split (dh=t>>7) + packed f32x2 reduce.
//   bx in [256,288)  : W transpose -> g_Wt (2 tiles each), wtcnt++
//   bx in [288,2336) : dep HALF-row: e=bx-288, row=e>>1, half=e&1;
//                      partial Sdep over 128 j's -> g_Sdep{A,B}, depcnt[row]++
// Per-out-block Wt traffic halves (128KB) -> exposed tail ~halves.
// ---------------------------------------------------------------------------
__global__ void __launch_bounds__(256, 4)
k_mega(const float* __restrict__ text,
       const float* __restrict__ adj,
       const float* __restrict__ dep,
       const float* __restrict__ W,
       const float* __restrict__ bias,
       float* __restrict__ out) {
    const int bx = blockIdx.x;
    const int t  = threadIdx.x;

    __shared__ __align__(16) char smraw[SMEM_SZ];

    // =========================== transpose role ===========================
    if (bx >= 256 && bx < 288) {
        float (*tile)[33] = (float (*)[33])smraw;
        const int tx = t & 31, ty = t >> 5;   // (32, 8)
#pragma unroll 1
        for (int pass = 0; pass < 2; pass++) {
            const int bb = (bx - 256) + pass * 32;
            const int d0 = (bb & 7) * 32, o0 = (bb >> 3) * 32;
#pragma unroll
            for (int k = 0; k < 32; k += 8)
                tile[ty + k][tx] = W[(o0 + ty + k) * DD + (d0 + tx)];
            __syncthreads();
#pragma unroll
            for (int k = 0; k < 32; k += 8)
                g_Wt[(d0 + ty + k) * DD + (o0 + tx)] = tile[tx][ty + k];
            __syncthreads();
        }
        __threadfence();
        __syncthreads();
        if (t == 0) atomicAdd((int*)&g_wtcnt, 1);
        return;
    }

    // ========================== dep half-row role ==========================
    if (bx >= 288) {
        const int e    = bx - 288;        // 0..2047
        const int id   = e >> 1;          // global row = b*256 + i
        const int half = e & 1;
        const int b    = id >> 8;
        const int i    = id & 255;
        const int jj   = t >> 6;
        const int d4   = t & 63;

        float*  adjs1 = (float*)smraw;                  // [256]
        float4* red   = (float4*)(smraw + 1024);        // [4][64]

        adjs1[t] = adj[(b * LL + i) * LL + t];
        __syncthreads();

        const int jbase = half * 128 + jj * 32;
        const float4* p = (const float4*)dep
                        + (((size_t)(b * LL + jbase) * LL + i) << 6) + d4;
        const size_t jstride = (size_t)LL << 6;   // 16384 float4 per j

        float4 acc = make_float4(0.f, 0.f, 0.f, 0.f);

#pragma unroll 1
        for (int js = 0; js < 32; js += 8) {
            float4 dv[8];
#pragma unroll
            for (int u = 0; u < 8; u++)
                dv[u] = __ldcs(p + (size_t)u * jstride);   // 8 LDG.128 in flight
            p += jstride * 8;
#pragma unroll
            for (int u = 0; u < 8; u++) {
                const float a = adjs1[jbase + js + u];
                acc.x += a * dv[u].x;
                acc.y += a * dv[u].y;
                acc.z += a * dv[u].z;
                acc.w += a * dv[u].w;
            }
        }

        red[(jj << 6) + d4] = acc;
        __syncthreads();
        if (t < 64) {
            float4 r0 = red[t], r1 = red[64 + t], r2 = red[128 + t], r3 = red[192 + t];
            float4 s;
            s.x = (r0.x + r1.x) + (r2.x + r3.x);
            s.y = (r0.y + r1.y) + (r2.y + r3.y);
            s.z = (r0.z + r1.z) + (r2.z + r3.z);
            s.w = (r0.w + r1.w) + (r2.w + r3.w);
            float* dst = half ? g_SdepB : g_SdepA;
            ((float4*)dst)[(id << 6) + t] = s;
        }
        __threadfence();      // release: partial visible before counter bump
        __syncthreads();
        if (t == 0) atomicAdd((int*)&g_depcnt[id], 1);
        return;
    }

    // ================== combined gemm -> wait -> out role ==================
    const int tile = bx >> 1;             // out tile 0..127
    const int nt   = bx & 1;              // output column half
    const int row0 = tile * 8;            // global rows row0..row0+7
    const int b    = row0 >> 8;

    float* Ss = (float*)smraw;                        // [8][264] after gemm
    float* Aa = (float*)(smraw + OFF_AA);             // [8]
    int*   lastf = (int*)(smraw + OFF_LASTF);

    {   // ---- S0 = adj @ text (8 rows, full d) -> smem, A -> smem ----
        float (*adjs)[LL] = (float (*)[LL])smraw;
        const float* adjg = adj + (size_t)row0 * LL;
#pragma unroll
        for (int r = 0; r < 8; r++) adjs[r][t] = adjg[r * LL + t];
        __syncthreads();

        {   // A row sums: warp w reduces adjs[w]
            const int warp = t >> 5, lane = t & 31;
            float s = 0.f;
#pragma unroll
            for (int k = 0; k < 8; k++) s += adjs[warp][lane + 32 * k];
#pragma unroll
            for (int off = 16; off; off >>= 1)
                s += __shfl_xor_sync(0xffffffffu, s, off);
            if (lane == 0) Aa[warp] = s;
        }

        const int o4 = t & 63;
        const int rg = t >> 6;
        const int r0 = rg * 2, r1 = r0 + 1;

        const float4* text4 = (const float4*)text + ((size_t)b * LL << 6) + o4;
        float4 acc0 = make_float4(0.f, 0.f, 0.f, 0.f);
        float4 acc1 = make_float4(0.f, 0.f, 0.f, 0.f);

#pragma unroll 1
        for (int j = 0; j < LL; j += 4) {
            float4 tv[4];
#pragma unroll
            for (int u = 0; u < 4; u++) tv[u] = text4[(j + u) << 6];
#pragma unroll
            for (int u = 0; u < 4; u++) {
                const float a0 = adjs[r0][j + u];
                const float a1 = adjs[r1][j + u];
                acc0.x += a0 * tv[u].x;  acc0.y += a0 * tv[u].y;
                acc0.z += a0 * tv[u].z;  acc0.w += a0 * tv[u].w;
                acc1.x += a1 * tv[u].x;  acc1.y += a1 * tv[u].y;
                acc1.z += a1 * tv[u].z;  acc1.w += a1 * tv[u].w;
            }
        }
        __syncthreads();   // all adjs reads done; safe to overwrite with Ssm
        *(float4*)&Ss[r0 * 264 + (o4 << 2)] = acc0;
        *(float4*)&Ss[r1 * 264 + (o4 << 2)] = acc1;
    }

    // ---- wait for Wt and both halves of our 8 rows ----
    if (t == 0) {
        while (g_wtcnt < 32) __nanosleep(128);
#pragma unroll 1
        for (int r = 0; r < 8; r++)
            while (g_depcnt[row0 + r] < 2) __nanosleep(128);
    }
    __syncthreads();
    __threadfence();   // acquire: order subsequent reads after flag observation

    // ---- S += SdepA + SdepB (8 rows) ----
    {
        const float4* Sa = (const float4*)(g_SdepA + (size_t)row0 * DD);
        const float4* Sb = (const float4*)(g_SdepB + (size_t)row0 * DD);
#pragma unroll
        for (int k = 0; k < 2; k++) {
            const int idx = t + 256 * k;
            const int rr = idx >> 6, cc = idx & 63;
            float4 ca = Sa[idx];
            float4 cb = Sb[idx];
            float4* pp = (float4*)&Ss[rr * 264 + (cc << 2)];
            float4 a = *pp;
            a.x += ca.x + cb.x;  a.y += ca.y + cb.y;
            a.z += ca.z + cb.z;  a.w += ca.w + cb.w;
            *pp = a;
        }
    }
    __syncthreads();

    // ---- out: 8 rows x 128 cols, d split across thread halves + f32x2 ----
    // dh = t>>7 covers d in [128dh,128dh+128); rq = (t>>5)&3 -> rows 2rq,2rq+1;
    // c4 = t&31 -> output float4 col nt*32 + c4. 8 phases of 16 d per half,
    // double-buffered smem Wt staging; final cross-half add via packed f32x2.
    {
        float4 (*Wts)[2][16][32] = (float4 (*)[2][16][32])(smraw + OFF_WTS);
        const int dh = t >> 7;
        const int rq = (t >> 5) & 3;
        const int c4 = t & 31;
        const int gc4 = nt * 32 + c4;
        const int rr0 = rq * 2, rr1 = rr0 + 1;
        const float4* Wtg = (const float4*)g_Wt;

        // staging decomposition for idx = t + 256k (k=0..3):
        // dhp = idx>>9, dloc = (idx>>5)&15, cc = idx&31
        float4 pre[4];
#pragma unroll
        for (int k = 0; k < 4; k++) {
            const int idx = t + 256 * k;
            const int dhp = idx >> 9, dloc = (idx >> 5) & 15, cc = idx & 31;
            pre[k] = Wtg[((dhp * 128 + dloc) << 6) + nt * 32 + cc];
        }

        unsigned long long aL0 = 0ull, aH0 = 0ull, aL1 = 0ull, aH1 = 0ull;

#pragma unroll 1
        for (int ph = 0; ph < 8; ph++) {
            const int buf = ph & 1;
#pragma unroll
            for (int k = 0; k < 4; k++) {
                const int idx = t + 256 * k;
                const int dhp = idx >> 9, dloc = (idx >> 5) & 15, cc = idx & 31;
                Wts[buf][dhp][dloc][cc] = pre[k];
            }
            __syncthreads();

            if (ph < 7) {
#pragma unroll
                for (int k = 0; k < 4; k++) {
                    const int idx = t + 256 * k;
                    const int dhp = idx >> 9, dloc = (idx >> 5) & 15, cc = idx & 31;
                    pre[k] = Wtg[((dhp * 128 + (ph + 1) * 16 + dloc) << 6)
                                 + nt * 32 + cc];
                }
            }

            const int dbase = dh * 128 + ph * 16;
#pragma unroll
            for (int dloc = 0; dloc < 16; dloc++) {
                const ulonglong2 w = *(const ulonglong2*)&Wts[buf][dh][dloc][c4];
                const unsigned long long sp0 = splat2(Ss[rr0 * 264 + dbase + dloc]);
                const unsigned long long sp1 = splat2(Ss[rr1 * 264 + dbase + dloc]);
                fma2(aL0, w.x, sp0);  fma2(aH0, w.y, sp0);
                fma2(aL1, w.x, sp1);  fma2(aH1, w.y, sp1);
            }
            __syncthreads();
        }

        // cross-half reduce: dh=1 publishes, dh=0 adds + writes out
        unsigned long long (*Red)[4] =
            (unsigned long long (*)[4])(smraw + OFF_WTS);
        if (dh == 1) {
            const int s = t & 127;
            Red[s][0] = aL0;  Red[s][1] = aH0;
            Red[s][2] = aL1;  Red[s][3] = aH1;
        }
        __syncthreads();
        if (dh == 0) {
            add2(aL0, Red[t][0]);  add2(aH0, Red[t][1]);
            add2(aL1, Red[t][2]);  add2(aH1, Red[t][3]);

            float4 res0, res1;
            unpk2(res0.x, res0.y, aL0);  unpk2(res0.z, res0.w, aH0);
            unpk2(res1.x, res1.y, aL1);  unpk2(res1.z, res1.w, aH1);

            const float4 bi = ((const float4*)bias)[gc4];
            const float  a0 = Aa[rr0];
            const float  a1 = Aa[rr1];
            res0.x += a0 * bi.x;  res0.y += a0 * bi.y;
            res0.z += a0 * bi.z;  res0.w += a0 * bi.w;
            res1.x += a1 * bi.x;  res1.y += a1 * bi.y;
            res1.z += a1 * bi.z;  res1.w += a1 * bi.w;

            ((float4*)(out + (size_t)(row0 + rr0) * DD))[gc4] = res0;
            ((float4*)(out + (size_t)(row0 + rr1) * DD))[gc4] = res1;
        }
    }

    // ---- last out block resets all sync state for the next graph replay ----
    __syncthreads();
    if (t == 0) *lastf = (atomicAdd(&g_outcnt, 1) == 255) ? 1 : 0;
    __syncthreads();
    if (*lastf) {
        for (int i = t; i < BB * LL; i += 256) g_depcnt[i] = 0;
        if (t == 0) { g_wtcnt = 0; g_outcnt = 0; }
    }
}

// ---------------------------------------------------------------------------
extern "C" void kernel_launch(void* const* d_in, const int* in_sizes, int n_in,
                              void* d_out, int out_size) {
    const float* text = (const float*)d_in[0];  // [4,256,256]
    const float* adj  = (const float*)d_in[1];  // [4,256,256]
    const float* dep  = (const float*)d_in[2];  // [4,256,256,256]
    const float* W    = (const float*)d_in[3];  // [256,256]
    const float* bias = (const float*)d_in[4];  // [256]
    float* out = (float*)d_out;                 // [4,256,256]

    k_mega<<<288 + 2 * BB * LL, 256>>>(text, adj, dep, W, bias, out);
}